// round 12
// baseline (speedup 1.0000x reference)
#include <cuda_runtime.h>
#include <cuda_fp16.h>
#include <math.h>
#include <stdint.h>

// ---------------- problem constants ----------------
#define HID 2048
#define NEXP 256
#define NGRP 8
#define TOPG 4
#define TOPK 8
#define RSCALE 2.5f
#define MT 64                  // tokens per CTA
#define KT 32                  // K per stage
#define NST (HID / KT)         // 64 stages
#define LSC 2048.0f            // lo-term scale (2^11), exact
#define ILSC (1.0f / 2048.0f)

// ---------------- smem layout ----------------
// A: 2 wm-groups x 2 buffers x 4KB (32 rows x 16 pairs, 128B/row, XOR swizzle)
// B: 16 warps x 3 buffers x 4KB (warp-private 32-expert slices, same layout)
#define A_SLICE 4096
#define B_SLICE 4096
#define OFF_BIAS 0
#define OFF_A 1024
#define OFF_B (OFF_A + 4 * A_SLICE)              // 17408
#define SMEM_TOTAL (OFF_B + 16 * 3 * B_SLICE)    // 214016
#define SC_STRIDE 260

// W pre-split: [256 rows][1024 pairs] of uint2 {hi16x2, lo16x2} = 2 MB
__device__ uint2 g_wpk[NEXP * (HID / 2)];

#define MMA16(d, a, b) asm volatile( \
    "mma.sync.aligned.m16n8k16.row.col.f32.f16.f16.f32 " \
    "{%0,%1,%2,%3},{%4,%5,%6,%7},{%8,%9},{%0,%1,%2,%3};" \
    : "+f"((d)[0]), "+f"((d)[1]), "+f"((d)[2]), "+f"((d)[3]) \
    : "r"((a)[0]), "r"((a)[1]), "r"((a)[2]), "r"((a)[3]), \
      "r"((b)[0]), "r"((b)[1]))

#define CPA(dst, src) asm volatile( \
    "cp.async.cg.shared.global [%0], [%1], 16;" :: "r"(dst), "l"(src) : "memory")
#define CPA_COMMIT asm volatile("cp.async.commit_group;" ::: "memory")
#define BARN(id) asm volatile("bar.sync %0, 256;" :: "r"(id) : "memory")

static __device__ __forceinline__ uint32_t s2u(const void* p) {
    uint32_t r;
    asm("{ .reg .u64 t; cvta.to.shared.u64 t, %1; cvt.u32.u64 %0, t; }" : "=r"(r) : "l"(p));
    return r;
}
static __device__ __forceinline__ uint32_t h2u(__half2 h) {
    return *(uint32_t*)&h;
}

// split 2 floats -> {hi f16x2, lo f16x2} (lo scaled by 2^11, exact unscale later)
static __device__ __forceinline__ uint2 packpair(float a, float b) {
    __half2 h = __floats2half2_rn(a, b);
    float2 f = __half22float2(h);
    __half2 l = __floats2half2_rn((a - f.x) * LSC, (b - f.y) * LSC);
    uint2 r; r.x = h2u(h); r.y = h2u(l);
    return r;
}

// ---------------------------------------------------------------------------
// One-time W split: fp32 [256,2048] -> interleaved {hi,lo} fp16x2 pairs.
// ---------------------------------------------------------------------------
extern "C" __global__ void split_w_kernel(const float* __restrict__ w,
                                          uint2* __restrict__ wpk)
{
    int id = blockIdx.x * 512 + threadIdx.x;        // 131072 float4s
    float4 v = ((const float4*)w)[id];
    wpk[id * 2 + 0] = packpair(v.x, v.y);
    wpk[id * 2 + 1] = packpair(v.z, v.w);
}

// ---------------------------------------------------------------------------
// Fused 3-term fp16 GEMM (64 x 256 x 2048 per CTA) + sigmoid + grouped top-k.
// NO CTA-wide barriers in mainloop: warp-private B pipelines (cp.async ring,
// depth 3, self-waited) + A shared per wm-group via named barriers (256 thr).
// 512 threads, 16 warps, 32x32 warp tiles, dual fp32 accumulators.
// ---------------------------------------------------------------------------
extern "C" __global__ void __launch_bounds__(512, 1)
gate_fused_kernel(const float* __restrict__ x,
                  const uint2* __restrict__ wpk,
                  const float* __restrict__ bias,
                  float* __restrict__ out, int N, int with_idx)
{
    extern __shared__ __align__(1024) char smem[];
    const uint32_t sb = s2u(smem);
    const int tid  = threadIdx.x;
    const int wid  = tid >> 5;
    const int lane = tid & 31;
    const int m0   = blockIdx.x * MT;
    const int wm   = wid & 1;      // 2 M-groups of 32 tokens
    const int wn   = wid >> 1;     // 8 N-groups of 32 experts
    const int gt   = (wid >> 1) * 32 + lane;   // id within wm-group [0,256)

    float* bs = (float*)(smem + OFF_BIAS);
    if (tid < NEXP) bs[tid] = bias[tid];
    __syncthreads();

    float accH[2][4][4], accL[2][4][4];
    #pragma unroll
    for (int i = 0; i < 2; i++)
        #pragma unroll
        for (int j = 0; j < 4; j++)
            #pragma unroll
            for (int c = 0; c < 4; c++) { accH[i][j][c] = 0.0f; accL[i][j][c] = 0.0f; }

    // ---- A producer mapping (per wm-group: 256 threads, 32 rows x 8 chunks) ----
    const int pa_row = gt >> 3;          // 0..31
    const int pa_cc  = gt & 7;           // chunk (2 pairs)
    const char* xrow = (const char*)(x + (size_t)(m0 + wm * 32 + pa_row) * HID + pa_cc * 4);
    const int pa_off = pa_row * 128 + (((pa_cc * 2) ^ ((pa_row & 3) << 2)) * 8);
    const uint32_t abase = sb + OFF_A + wm * (2 * A_SLICE);

    // ---- B warp-private cp.async mapping ----
    const uint32_t bbase = sb + OFF_B + wid * (3 * B_SLICE);

    auto ldgA = [&](int s) {
        return *(const float4*)(xrow + (size_t)s * KT * 4);
    };
    auto stsA = [&](int s, float4 v) {
        uint2 p0 = packpair(v.x, v.y);
        uint2 p1 = packpair(v.z, v.w);
        uint4 o4; o4.x = p0.x; o4.y = p0.y; o4.z = p1.x; o4.w = p1.y;
        *(uint4*)(smem + OFF_A + wm * (2 * A_SLICE) + (s & 1) * A_SLICE + pa_off) = o4;
    };
    auto cpaB = [&](int s) {
        const uint32_t buf = bbase + (s % 3) * B_SLICE;
        #pragma unroll
        for (int i = 0; i < 8; i++) {
            int idx = i * 32 + lane;
            int r = idx >> 3, cc = idx & 7;
            uint32_t dst = buf + r * 128 + (((cc * 2) ^ ((r & 3) << 2)) * 8);
            CPA(dst, wpk + (size_t)(wn * 32 + r) * (HID / 2) + s * 16 + cc * 2);
        }
        CPA_COMMIT;
    };

    auto compute = [&](int s) {
        const char* A = smem + OFF_A + wm * (2 * A_SLICE) + (s & 1) * A_SLICE;
        const char* B = smem + OFF_B + wid * (3 * B_SLICE) + (s % 3) * B_SLICE;
        const int t = lane & 3, g = lane >> 2;
        #pragma unroll
        for (int c = 0; c < 2; c++) {
            const int perm8 = ((c * 8 + t) ^ ((g & 3) << 2)) * 8;
            uint32_t ah[2][4], al[2][4];
            #pragma unroll
            for (int mi = 0; mi < 2; mi++) {
                int o0 = (mi * 16 + g) * 128 + perm8;
                uint2 u0 = *(const uint2*)(A + o0);
                uint2 u1 = *(const uint2*)(A + o0 + 1024);
                uint2 u2 = *(const uint2*)(A + (o0 ^ 32));
                uint2 u3 = *(const uint2*)(A + ((o0 + 1024) ^ 32));
                ah[mi][0] = u0.x; al[mi][0] = u0.y;
                ah[mi][1] = u1.x; al[mi][1] = u1.y;
                ah[mi][2] = u2.x; al[mi][2] = u2.y;
                ah[mi][3] = u3.x; al[mi][3] = u3.y;
            }
            uint32_t bh[4][2], bl[4][2];
            #pragma unroll
            for (int ni = 0; ni < 4; ni++) {
                int ob = (ni * 8 + g) * 128 + perm8;
                uint2 v0 = *(const uint2*)(B + ob);
                uint2 v1 = *(const uint2*)(B + (ob ^ 32));
                bh[ni][0] = v0.x; bl[ni][0] = v0.y;
                bh[ni][1] = v1.x; bl[ni][1] = v1.y;
            }
            #pragma unroll
            for (int ni = 0; ni < 4; ni++)
                #pragma unroll
                for (int mi = 0; mi < 2; mi++)
                    MMA16(accH[mi][ni], ah[mi], bh[ni]);   // exact hi*hi
            #pragma unroll
            for (int ni = 0; ni < 4; ni++)
                #pragma unroll
                for (int mi = 0; mi < 2; mi++)
                    MMA16(accL[mi][ni], al[mi], bh[ni]);
            #pragma unroll
            for (int ni = 0; ni < 4; ni++)
                #pragma unroll
                for (int mi = 0; mi < 2; mi++)
                    MMA16(accL[mi][ni], ah[mi], bl[ni]);
        }
    };

    // ---- prologue ----
    const int barid = 1 + wm;
    cpaB(0);
    cpaB(1);
    float4 av = ldgA(0);
    stsA(0, av);
    av = ldgA(1);
    BARN(barid);                 // publish A(0)

    // ---- mainloop: no __syncthreads ----
    for (int s = 0; s < NST; s++) {
        if (s + 2 < NST) cpaB(s + 2);          // buf (s+2)%3: self finished s-1
        if (s + 2 < NST)      { asm volatile("cp.async.wait_group 2;" ::: "memory"); }
        else if (s + 1 < NST) { asm volatile("cp.async.wait_group 1;" ::: "memory"); }
        else                  { asm volatile("cp.async.wait_group 0;" ::: "memory"); }
        BARN(barid);                           // group compute(s-1) done -> Abuf[(s+1)&1] free
        if (s + 1 < NST) stsA(s + 1, av);
        if (s + 2 < NST) av = ldgA(s + 2);
        BARN(barid);                           // A(s+1) published; A(s) long since visible
        compute(s);
    }
    __syncthreads();   // all warps done; tiles dead -> scores overlay

    // ---- epilogue: combine acc (unscale lo), +bias, sigmoid, overlay ----
    float* sc = (float*)(smem + OFF_A);
    #pragma unroll
    for (int mi = 0; mi < 2; mi++) {
        int tr = wm * 32 + mi * 16 + (lane >> 2);
        #pragma unroll
        for (int ni = 0; ni < 4; ni++) {
            int e = wn * 32 + ni * 8 + (lane & 3) * 2;
            float s0 = fmaf(accL[mi][ni][0], ILSC, accH[mi][ni][0]) + bs[e];
            float s1 = fmaf(accL[mi][ni][1], ILSC, accH[mi][ni][1]) + bs[e + 1];
            float s2 = fmaf(accL[mi][ni][2], ILSC, accH[mi][ni][2]) + bs[e];
            float s3 = fmaf(accL[mi][ni][3], ILSC, accH[mi][ni][3]) + bs[e + 1];
            float2 v0, v1;
            v0.x = 1.0f / (1.0f + expf(-s0));
            v0.y = 1.0f / (1.0f + expf(-s1));
            v1.x = 1.0f / (1.0f + expf(-s2));
            v1.y = 1.0f / (1.0f + expf(-s3));
            *(float2*)&sc[tr * SC_STRIDE + e]       = v0;
            *(float2*)&sc[(tr + 8) * SC_STRIDE + e] = v1;
        }
    }
    __syncthreads();

    // ---- routing: warp per token, 4 tokens per warp ----
    for (int it = 0; it < 4; it++) {
        const int t = wid * 4 + it;
        const float* row = sc + t * SC_STRIDE;

        float orig[NGRP], rsc[NGRP];
        #pragma unroll
        for (int s = 0; s < NGRP; s++) {
            float sg = row[s * 32 + lane];
            orig[s] = sg;
            rsc[s] = sg + bs[s * 32 + lane];
        }

        // group score = top-2 sum (ties -> lower expert index)
        float gs[NGRP];
        #pragma unroll
        for (int g = 0; g < NGRP; g++) {
            float m1 = rsc[g];
            int l1 = lane;
            #pragma unroll
            for (int off = 16; off >= 1; off >>= 1) {
                float ov = __shfl_xor_sync(0xffffffffu, m1, off);
                int ol = __shfl_xor_sync(0xffffffffu, l1, off);
                if (ov > m1 || (ov == m1 && ol < l1)) { m1 = ov; l1 = ol; }
            }
            float v2 = (lane == l1) ? -INFINITY : rsc[g];
            #pragma unroll
            for (int off = 16; off >= 1; off >>= 1)
                v2 = fmaxf(v2, __shfl_xor_sync(0xffffffffu, v2, off));
            gs[g] = m1 + v2;
        }

        // keep top-4 groups (ties -> lower group index)
        float mv[NGRP];
        #pragma unroll
        for (int g = 0; g < NGRP; g++) {
            int cnt = 0;
            #pragma unroll
            for (int h = 0; h < NGRP; h++)
                cnt += (gs[h] > gs[g]) || (gs[h] == gs[g] && h < g);
            mv[g] = (cnt < TOPG) ? rsc[g] : -INFINITY;
        }

        // iterative top-8 (ties -> lower expert index)
        float wsel[TOPK];
        int esel[TOPK];
        #pragma unroll
        for (int k = 0; k < TOPK; k++) {
            float bv2 = -INFINITY; int be = NEXP; float bo = 0.0f;
            #pragma unroll
            for (int s = 0; s < NGRP; s++)
                if (mv[s] > bv2) { bv2 = mv[s]; be = s * 32 + lane; bo = orig[s]; }
            #pragma unroll
            for (int off = 16; off >= 1; off >>= 1) {
                float ov = __shfl_xor_sync(0xffffffffu, bv2, off);
                int oe = __shfl_xor_sync(0xffffffffu, be, off);
                float oo = __shfl_xor_sync(0xffffffffu, bo, off);
                if (ov > bv2 || (ov == bv2 && oe < be)) { bv2 = ov; be = oe; bo = oo; }
            }
            wsel[k] = bo;
            esel[k] = be;
            if ((be & 31) == lane) {
                int bslot = be >> 5;
                #pragma unroll
                for (int s = 0; s < NGRP; s++)
                    if (s == bslot) mv[s] = -INFINITY;
            }
        }

        float tot = 0.0f;
        #pragma unroll
        for (int k = 0; k < TOPK; k++) tot += wsel[k];
        float inv = RSCALE / tot;

        const int gtk = m0 + t;
        #pragma unroll
        for (int k = 0; k < TOPK; k++) {
            if (lane == k) {
                out[(size_t)gtk * TOPK + k] = wsel[k] * inv;
                if (with_idx)
                    out[(size_t)N * TOPK + (size_t)gtk * TOPK + k] = (float)esel[k];
            }
        }
    }
}

// ---------------------------------------------------------------------------
extern "C" void kernel_launch(void* const* d_in, const int* in_sizes, int n_in,
                              void* d_out, int out_size)
{
    const float* x    = (const float*)d_in[0];
    const float* w    = (const float*)d_in[1];
    const float* bias = (const float*)d_in[2];
    float* out = (float*)d_out;

    int N = in_sizes[0] / HID;
    int with_idx = (out_size >= 2 * N * TOPK) ? 1 : 0;

    uint2* wpk = nullptr;
    cudaGetSymbolAddress((void**)&wpk, g_wpk);

    split_w_kernel<<<NEXP * HID / 4 / 512, 512>>>(w, wpk);

    cudaFuncSetAttribute(gate_fused_kernel,
                         cudaFuncAttributeMaxDynamicSharedMemorySize, SMEM_TOTAL);
    gate_fused_kernel<<<N / MT, 512, SMEM_TOTAL>>>(x, wpk, bias, out, N, with_idx);
}

// round 13
// speedup vs baseline: 1.0215x; 1.0215x over previous
#include <cuda_runtime.h>
#include <cuda_fp16.h>
#include <math.h>
#include <stdint.h>

// ---------------- problem constants ----------------
#define HID 2048
#define NEXP 256
#define NGRP 8
#define TOPG 4
#define TOPK 8
#define RSCALE 2.5f
#define MT 32                  // tokens per CTA (2 CTAs co-resident per SM)
#define KT 32                  // K per smem stage
#define NST (HID / KT)         // 64 stages
#define LSC 2048.0f            // lo-term scale (2^11), exact
#define ILSC (1.0f / 2048.0f)

// ---------------- packed fp16 smem layout ----------------
// per row 16 pairs; words [2p]=hi f16x2, [2p+1]=lo f16x2; stride 40 words.
// rows 0..31 = A (tokens), rows 32..287 = B (experts).
#define RSPK 40
#define OFF_BIAS 0
#define OFF_PK 1024
#define PKSTAGE (288 * RSPK * 4)                 // 46080
#define SMEM_TOTAL (OFF_PK + 2 * PKSTAGE)        // 93184  (x2 CTAs = 186KB < 228KB)
#define SC_STRIDE 260

// W pre-split: [256 rows][1024 pairs] of uint2 {hi16x2, lo16x2} = 2 MB
__device__ uint2 g_wpk[NEXP * (HID / 2)];

#define MMA16(d, a, b) asm volatile( \
    "mma.sync.aligned.m16n8k16.row.col.f32.f16.f16.f32 " \
    "{%0,%1,%2,%3},{%4,%5,%6,%7},{%8,%9},{%0,%1,%2,%3};" \
    : "+f"((d)[0]), "+f"((d)[1]), "+f"((d)[2]), "+f"((d)[3]) \
    : "r"((a)[0]), "r"((a)[1]), "r"((a)[2]), "r"((a)[3]), \
      "r"((b)[0]), "r"((b)[1]))

#define CPA(dst, src) asm volatile( \
    "cp.async.cg.shared.global [%0], [%1], 16;" :: "r"(dst), "l"(src) : "memory")
#define CPA_COMMIT asm volatile("cp.async.commit_group;" ::: "memory")

static __device__ __forceinline__ uint32_t s2u(const void* p) {
    uint32_t r;
    asm("{ .reg .u64 t; cvta.to.shared.u64 t, %1; cvt.u32.u64 %0, t; }" : "=r"(r) : "l"(p));
    return r;
}
static __device__ __forceinline__ uint32_t h2u(__half2 h) {
    return *(uint32_t*)&h;
}

// split 2 floats -> {hi f16x2, lo f16x2} (lo scaled by 2^11, exact unscale later)
static __device__ __forceinline__ uint2 packpair(float a, float b) {
    __half2 h = __floats2half2_rn(a, b);
    float2 f = __half22float2(h);
    __half2 l = __floats2half2_rn((a - f.x) * LSC, (b - f.y) * LSC);
    uint2 r; r.x = h2u(h); r.y = h2u(l);
    return r;
}

// ---------------------------------------------------------------------------
// One-time W split: fp32 [256,2048] -> interleaved {hi,lo} fp16x2 pairs.
// ---------------------------------------------------------------------------
extern "C" __global__ void split_w_kernel(const float* __restrict__ w,
                                          uint2* __restrict__ wpk)
{
    int id = blockIdx.x * 512 + threadIdx.x;        // 131072 float4s
    float4 v = ((const float4*)w)[id];
    wpk[id * 2 + 0] = packpair(v.x, v.y);
    wpk[id * 2 + 1] = packpair(v.z, v.w);
}

// ---------------------------------------------------------------------------
// Fused: 3-term fp16 mma.sync GEMM (32 x 256 x 2048 per CTA), dual fp32
// accumulators, B pre-split (cp.async packed), A split in registers.
// 256 threads, 8 warps (32x32 warp tiles), 2 CTAs/SM so stage barriers of one
// CTA are hidden by the other CTA's compute. + sigmoid + grouped top-k.
// ---------------------------------------------------------------------------
extern "C" __global__ void __launch_bounds__(256, 2)
gate_fused_kernel(const float* __restrict__ x,
                  const uint2* __restrict__ wpk,
                  const float* __restrict__ bias,
                  float* __restrict__ out, int N, int with_idx)
{
    extern __shared__ __align__(1024) char smem[];
    const uint32_t sb = s2u(smem);
    const int tid  = threadIdx.x;
    const int wid  = tid >> 5;     // 0..7 = expert group
    const int lane = tid & 31;
    const int m0   = blockIdx.x * MT;
    const int wn   = wid;          // 8 N-groups of 32 experts

    float* bs = (float*)(smem + OFF_BIAS);
    bs[tid] = bias[tid];           // 256 threads == NEXP

    float accH[2][4][4], accL[2][4][4];
    #pragma unroll
    for (int i = 0; i < 2; i++)
        #pragma unroll
        for (int j = 0; j < 4; j++)
            #pragma unroll
            for (int c = 0; c < 4; c++) { accH[i][j][c] = 0.0f; accL[i][j][c] = 0.0f; }

    const int arow = tid >> 3;     // 0..31 (A row)
    const int achk = tid & 7;      // float4 chunk within 32-float k-slab

    // ---- A: one float4 per thread per stage ----
    auto ldgA = [&](int s) {
        return *(const float4*)(x + (size_t)(m0 + arow) * HID + s * KT + achk * 4);
    };
    // ---- A: register split -> packed STS ----
    auto stsA = [&](int s, float4 v) {
        uint32_t* pk = (uint32_t*)(smem + OFF_PK + (s & 1) * PKSTAGE);
        uint2 p0 = packpair(v.x, v.y);
        uint2 p1 = packpair(v.z, v.w);
        uint4 o4; o4.x = p0.x; o4.y = p0.y; o4.z = p1.x; o4.w = p1.y;
        *(uint4*)(pk + arow * RSPK + achk * 4) = o4;
    };
    // ---- B: cp.async packed tile (256 rows x 16 pairs = 32KB) ----
    auto cpaB = [&](int s) {
        const uint32_t bufa = sb + OFF_PK + (s & 1) * PKSTAGE;
        #pragma unroll
        for (int i = 0; i < 8; i++) {
            int id = tid + i * 256;            // 2048 16B-chunks
            int row = id >> 3, c = id & 7;
            uint32_t dst = bufa + (uint32_t)((MT + row) * RSPK + c * 4) * 4;
            CPA(dst, wpk + (size_t)row * (HID / 2) + s * 16 + 2 * c);
        }
        CPA_COMMIT;
    };

    auto compute = [&](int s) {
        const uint32_t* pk = (const uint32_t*)(smem + OFF_PK + (s & 1) * PKSTAGE);
        #pragma unroll
        for (int c = 0; c < 2; c++) {          // two k16 chunks per stage
            const int pbase = (c * 8 + (lane & 3)) * 2;
            uint32_t ah[2][4], al[2][4];
            #pragma unroll
            for (int mi = 0; mi < 2; mi++) {
                int r = mi * 16 + (lane >> 2);
                int o = r * RSPK + pbase;
                uint2 w0 = *(const uint2*)(pk + o);
                uint2 w1 = *(const uint2*)(pk + o + 8 * RSPK);
                uint2 w2 = *(const uint2*)(pk + o + 8);
                uint2 w3 = *(const uint2*)(pk + o + 8 * RSPK + 8);
                ah[mi][0] = w0.x; al[mi][0] = w0.y;
                ah[mi][1] = w1.x; al[mi][1] = w1.y;
                ah[mi][2] = w2.x; al[mi][2] = w2.y;
                ah[mi][3] = w3.x; al[mi][3] = w3.y;
            }
            #pragma unroll
            for (int np = 0; np < 2; np++) {   // pairs of n8 tiles
                uint32_t bh[2][2], bl[2][2];
                #pragma unroll
                for (int j = 0; j < 2; j++) {
                    int e = wn * 32 + (np * 2 + j) * 8 + (lane >> 2);
                    int o = (MT + e) * RSPK + pbase;
                    uint2 u0 = *(const uint2*)(pk + o);
                    uint2 u1 = *(const uint2*)(pk + o + 8);
                    bh[j][0] = u0.x; bl[j][0] = u0.y;
                    bh[j][1] = u1.x; bl[j][1] = u1.y;
                }
                #pragma unroll
                for (int mi = 0; mi < 2; mi++)
                    #pragma unroll
                    for (int j = 0; j < 2; j++)
                        MMA16(accH[mi][np * 2 + j], ah[mi], bh[j]);   // exact hi*hi
                #pragma unroll
                for (int mi = 0; mi < 2; mi++)
                    #pragma unroll
                    for (int j = 0; j < 2; j++)
                        MMA16(accL[mi][np * 2 + j], al[mi], bh[j]);
                #pragma unroll
                for (int mi = 0; mi < 2; mi++)
                    #pragma unroll
                    for (int j = 0; j < 2; j++)
                        MMA16(accL[mi][np * 2 + j], ah[mi], bl[j]);
            }
        }
    };

    // ---- pipelined main loop: one barrier per stage ----
    float4 avA = ldgA(0);
    float4 avB = ldgA(1);
    cpaB(0);
    stsA(0, avA);
    for (int s = 0; s < NST; s++) {
        asm volatile("cp.async.wait_group 0;" ::: "memory");
        __syncthreads();     // B(s) visible; A(s) STS visible; compute(s-1) done
        if (s + 1 < NST) {
            cpaB(s + 1);                          // buf[(s+1)&1]: compute(s-1) done with it
            stsA(s + 1, (s & 1) ? avA : avB);
            if (s + 2 < NST) {
                if (s & 1) avB = ldgA(s + 2);
                else       avA = ldgA(s + 2);
            }
        }
        compute(s);
    }
    __syncthreads();   // tiles dead; reuse smem for scores overlay

    // ---- epilogue: combine acc (unscale lo), +bias, sigmoid, overlay ----
    float* sc = (float*)(smem + OFF_PK);
    #pragma unroll
    for (int mi = 0; mi < 2; mi++) {
        int tr = mi * 16 + (lane >> 2);
        #pragma unroll
        for (int ni = 0; ni < 4; ni++) {
            int e = wn * 32 + ni * 8 + (lane & 3) * 2;
            float s0 = fmaf(accL[mi][ni][0], ILSC, accH[mi][ni][0]) + bs[e];
            float s1 = fmaf(accL[mi][ni][1], ILSC, accH[mi][ni][1]) + bs[e + 1];
            float s2 = fmaf(accL[mi][ni][2], ILSC, accH[mi][ni][2]) + bs[e];
            float s3 = fmaf(accL[mi][ni][3], ILSC, accH[mi][ni][3]) + bs[e + 1];
            float2 v0, v1;
            v0.x = 1.0f / (1.0f + expf(-s0));
            v0.y = 1.0f / (1.0f + expf(-s1));
            v1.x = 1.0f / (1.0f + expf(-s2));
            v1.y = 1.0f / (1.0f + expf(-s3));
            *(float2*)&sc[tr * SC_STRIDE + e]       = v0;
            *(float2*)&sc[(tr + 8) * SC_STRIDE + e] = v1;
        }
    }
    __syncthreads();

    // ---- routing: warp per token, 4 tokens per warp ----
    for (int it = 0; it < 4; it++) {
        const int t = wid * 4 + it;
        const float* row = sc + t * SC_STRIDE;

        float orig[NGRP], rsc[NGRP];
        #pragma unroll
        for (int s = 0; s < NGRP; s++) {
            float sg = row[s * 32 + lane];
            orig[s] = sg;
            rsc[s] = sg + bs[s * 32 + lane];
        }

        // group score = top-2 sum (ties -> lower expert index)
        float gs[NGRP];
        #pragma unroll
        for (int g = 0; g < NGRP; g++) {
            float m1 = rsc[g];
            int l1 = lane;
            #pragma unroll
            for (int off = 16; off >= 1; off >>= 1) {
                float ov = __shfl_xor_sync(0xffffffffu, m1, off);
                int ol = __shfl_xor_sync(0xffffffffu, l1, off);
                if (ov > m1 || (ov == m1 && ol < l1)) { m1 = ov; l1 = ol; }
            }
            float v2 = (lane == l1) ? -INFINITY : rsc[g];
            #pragma unroll
            for (int off = 16; off >= 1; off >>= 1)
                v2 = fmaxf(v2, __shfl_xor_sync(0xffffffffu, v2, off));
            gs[g] = m1 + v2;
        }

        // keep top-4 groups (ties -> lower group index)
        float mv[NGRP];
        #pragma unroll
        for (int g = 0; g < NGRP; g++) {
            int cnt = 0;
            #pragma unroll
            for (int h = 0; h < NGRP; h++)
                cnt += (gs[h] > gs[g]) || (gs[h] == gs[g] && h < g);
            mv[g] = (cnt < TOPG) ? rsc[g] : -INFINITY;
        }

        // iterative top-8 (ties -> lower expert index)
        float wsel[TOPK];
        int esel[TOPK];
        #pragma unroll
        for (int k = 0; k < TOPK; k++) {
            float bv2 = -INFINITY; int be = NEXP; float bo = 0.0f;
            #pragma unroll
            for (int s = 0; s < NGRP; s++)
                if (mv[s] > bv2) { bv2 = mv[s]; be = s * 32 + lane; bo = orig[s]; }
            #pragma unroll
            for (int off = 16; off >= 1; off >>= 1) {
                float ov = __shfl_xor_sync(0xffffffffu, bv2, off);
                int oe = __shfl_xor_sync(0xffffffffu, be, off);
                float oo = __shfl_xor_sync(0xffffffffu, bo, off);
                if (ov > bv2 || (ov == bv2 && oe < be)) { bv2 = ov; be = oe; bo = oo; }
            }
            wsel[k] = bo;
            esel[k] = be;
            if ((be & 31) == lane) {
                int bslot = be >> 5;
                #pragma unroll
                for (int s = 0; s < NGRP; s++)
                    if (s == bslot) mv[s] = -INFINITY;
            }
        }

        float tot = 0.0f;
        #pragma unroll
        for (int k = 0; k < TOPK; k++) tot += wsel[k];
        float inv = RSCALE / tot;

        const int gt = m0 + t;
        #pragma unroll
        for (int k = 0; k < TOPK; k++) {
            if (lane == k) {
                out[(size_t)gt * TOPK + k] = wsel[k] * inv;
                if (with_idx)
                    out[(size_t)N * TOPK + (size_t)gt * TOPK + k] = (float)esel[k];
            }
        }
    }
}

// ---------------------------------------------------------------------------
extern "C" void kernel_launch(void* const* d_in, const int* in_sizes, int n_in,
                              void* d_out, int out_size)
{
    const float* x    = (const float*)d_in[0];
    const float* w    = (const float*)d_in[1];
    const float* bias = (const float*)d_in[2];
    float* out = (float*)d_out;

    int N = in_sizes[0] / HID;
    int with_idx = (out_size >= 2 * N * TOPK) ? 1 : 0;

    uint2* wpk = nullptr;
    cudaGetSymbolAddress((void**)&wpk, g_wpk);

    split_w_kernel<<<NEXP * HID / 4 / 512, 512>>>(w, wpk);

    cudaFuncSetAttribute(gate_fused_kernel,
                         cudaFuncAttributeMaxDynamicSharedMemorySize, SMEM_TOTAL);
    gate_fused_kernel<<<N / MT, 256, SMEM_TOTAL>>>(x, wpk, bias, out, N, with_idx);
}

// round 14
// speedup vs baseline: 1.0648x; 1.0424x over previous
#include <cuda_runtime.h>
#include <cuda_fp16.h>
#include <math.h>
#include <stdint.h>

// ---------------- problem constants ----------------
#define HID 2048
#define NEXP 256
#define NGRP 8
#define TOPG 4
#define TOPK 8
#define RSCALE 2.5f
#define MT 64                  // tokens per CTA
#define KT 64                  // K per smem stage
#define NST (HID / KT)         // 32 stages
#define LSC 2048.0f            // lo-term scale (2^11), exact
#define ILSC (1.0f / 2048.0f)

// ---------------- packed fp16 smem layout ----------------
// per row 32 pairs; words [2p]=hi f16x2, [2p+1]=lo f16x2; stride 72 words.
// rows 0..63 = A (tokens), rows 64..319 = B (experts).
#define RSPK 72
#define OFF_BIAS 0
#define OFF_PK 1024
#define PKSTAGE (320 * RSPK * 4)                 // 92160
#define SMEM_TOTAL (OFF_PK + 2 * PKSTAGE)        // 185344
#define SC_STRIDE 260

// W pre-split: [256 rows][1024 pairs] of uint2 {hi16x2, lo16x2} = 2 MB
__device__ uint2 g_wpk[NEXP * (HID / 2)];

#define MMA16(d, a, b) asm volatile( \
    "mma.sync.aligned.m16n8k16.row.col.f32.f16.f16.f32 " \
    "{%0,%1,%2,%3},{%4,%5,%6,%7},{%8,%9},{%0,%1,%2,%3};" \
    : "+f"((d)[0]), "+f"((d)[1]), "+f"((d)[2]), "+f"((d)[3]) \
    : "r"((a)[0]), "r"((a)[1]), "r"((a)[2]), "r"((a)[3]), \
      "r"((b)[0]), "r"((b)[1]))

#define CPA(dst, src) asm volatile( \
    "cp.async.cg.shared.global [%0], [%1], 16;" :: "r"(dst), "l"(src) : "memory")
#define CPA_COMMIT asm volatile("cp.async.commit_group;" ::: "memory")

static __device__ __forceinline__ uint32_t s2u(const void* p) {
    uint32_t r;
    asm("{ .reg .u64 t; cvta.to.shared.u64 t, %1; cvt.u32.u64 %0, t; }" : "=r"(r) : "l"(p));
    return r;
}
static __device__ __forceinline__ uint32_t h2u(__half2 h) {
    return *(uint32_t*)&h;
}

// split 2 floats -> {hi f16x2, lo f16x2} (lo scaled by 2^11, exact unscale later)
static __device__ __forceinline__ uint2 packpair(float a, float b) {
    __half2 h = __floats2half2_rn(a, b);
    float2 f = __half22float2(h);
    __half2 l = __floats2half2_rn((a - f.x) * LSC, (b - f.y) * LSC);
    uint2 r; r.x = h2u(h); r.y = h2u(l);
    return r;
}

// ---------------------------------------------------------------------------
// One-time W split: fp32 [256,2048] -> interleaved {hi,lo} fp16x2 pairs.
// ---------------------------------------------------------------------------
extern "C" __global__ void split_w_kernel(const float* __restrict__ w,
                                          uint2* __restrict__ wpk)
{
    int id = blockIdx.x * 512 + threadIdx.x;        // 131072 float4s
    float4 v = ((const float4*)w)[id];
    wpk[id * 2 + 0] = packpair(v.x, v.y);
    wpk[id * 2 + 1] = packpair(v.z, v.w);
}

// ---------------------------------------------------------------------------
// Fused: 3-term fp16 mma.sync GEMM (64 x 256 x 2048 per CTA), dual fp32
// accumulators, B pre-split (cp.async packed), A split in registers.
// 256 threads, 8 warps, FAT 32x64 warp tiles, KT=64 (one barrier / 64-K).
// + sigmoid + grouped top-k routing.
// ---------------------------------------------------------------------------
extern "C" __global__ void __launch_bounds__(256, 1)
gate_fused_kernel(const float* __restrict__ x,
                  const uint2* __restrict__ wpk,
                  const float* __restrict__ bias,
                  float* __restrict__ out, int N, int with_idx)
{
    extern __shared__ __align__(1024) char smem[];
    const uint32_t sb = s2u(smem);
    const int tid  = threadIdx.x;
    const int wid  = tid >> 5;
    const int lane = tid & 31;
    const int m0   = blockIdx.x * MT;
    const int wm   = wid & 1;      // 2 M-groups of 32 tokens
    const int wn   = wid >> 1;     // 4 N-groups of 64 experts

    float* bs = (float*)(smem + OFF_BIAS);
    bs[tid] = bias[tid];           // 256 threads == NEXP

    float accH[2][8][4], accL[2][8][4];
    #pragma unroll
    for (int i = 0; i < 2; i++)
        #pragma unroll
        for (int j = 0; j < 8; j++)
            #pragma unroll
            for (int c = 0; c < 4; c++) { accH[i][j][c] = 0.0f; accL[i][j][c] = 0.0f; }

    const int arow = tid >> 2;     // 0..63 (A row)
    const int achk = tid & 3;      // base float4 chunk; covers achk+4i, i<4

    float4 av[4];                  // A prefetch: 4 float4 per thread per stage

    auto ldgA = [&](int s) {
        const float* p = x + (size_t)(m0 + arow) * HID + s * KT;
        #pragma unroll
        for (int i = 0; i < 4; i++)
            av[i] = *(const float4*)(p + (achk + 4 * i) * 4);
    };
    // A: register split -> packed STS (4 uint4 per thread)
    auto stsA = [&](int s) {
        uint32_t* pk = (uint32_t*)(smem + OFF_PK + (s & 1) * PKSTAGE);
        #pragma unroll
        for (int i = 0; i < 4; i++) {
            uint2 p0 = packpair(av[i].x, av[i].y);
            uint2 p1 = packpair(av[i].z, av[i].w);
            uint4 o4; o4.x = p0.x; o4.y = p0.y; o4.z = p1.x; o4.w = p1.y;
            *(uint4*)(pk + arow * RSPK + (achk + 4 * i) * 4) = o4;
        }
    };
    // B: cp.async packed tile (256 rows x 32 pairs = 64KB)
    auto cpaB = [&](int s) {
        const uint32_t bufa = sb + OFF_PK + (s & 1) * PKSTAGE;
        #pragma unroll
        for (int i = 0; i < 16; i++) {
            int id = tid + i * 256;            // 4096 16B-chunks
            int row = id >> 4, c = id & 15;
            uint32_t dst = bufa + (uint32_t)((MT + row) * RSPK + c * 4) * 4;
            CPA(dst, wpk + (size_t)row * (HID / 2) + s * 32 + 2 * c);
        }
        CPA_COMMIT;
    };

    auto compute = [&](int s) {
        const uint32_t* pk = (const uint32_t*)(smem + OFF_PK + (s & 1) * PKSTAGE);
        #pragma unroll
        for (int c = 0; c < 4; c++) {          // four k16 chunks per stage
            const int pbase = (c * 8 + (lane & 3)) * 2;
            uint32_t ah[2][4], al[2][4];
            #pragma unroll
            for (int mi = 0; mi < 2; mi++) {
                int r = wm * 32 + mi * 16 + (lane >> 2);
                int o = r * RSPK + pbase;
                uint2 w0 = *(const uint2*)(pk + o);
                uint2 w1 = *(const uint2*)(pk + o + 8 * RSPK);
                uint2 w2 = *(const uint2*)(pk + o + 8);
                uint2 w3 = *(const uint2*)(pk + o + 8 * RSPK + 8);
                ah[mi][0] = w0.x; al[mi][0] = w0.y;
                ah[mi][1] = w1.x; al[mi][1] = w1.y;
                ah[mi][2] = w2.x; al[mi][2] = w2.y;
                ah[mi][3] = w3.x; al[mi][3] = w3.y;
            }
            // B frags: 8 n8-blocks = 64 experts
            uint32_t bh[8][2], bl[8][2];
            #pragma unroll
            for (int ni = 0; ni < 8; ni++) {
                int e = wn * 64 + ni * 8 + (lane >> 2);
                int o = (MT + e) * RSPK + pbase;
                uint2 u0 = *(const uint2*)(pk + o);
                uint2 u1 = *(const uint2*)(pk + o + 8);
                bh[ni][0] = u0.x; bl[ni][0] = u0.y;
                bh[ni][1] = u1.x; bl[ni][1] = u1.y;
            }
            // term-major: 16 MMAs between same-accumulator reuse
            #pragma unroll
            for (int ni = 0; ni < 8; ni++)
                #pragma unroll
                for (int mi = 0; mi < 2; mi++)
                    MMA16(accH[mi][ni], ah[mi], bh[ni]);   // exact hi*hi
            #pragma unroll
            for (int ni = 0; ni < 8; ni++)
                #pragma unroll
                for (int mi = 0; mi < 2; mi++)
                    MMA16(accL[mi][ni], al[mi], bh[ni]);
            #pragma unroll
            for (int ni = 0; ni < 8; ni++)
                #pragma unroll
                for (int mi = 0; mi < 2; mi++)
                    MMA16(accL[mi][ni], ah[mi], bl[ni]);
        }
    };

    // ---- pipelined main loop: one barrier per 64-K stage ----
    cpaB(0);
    ldgA(0);
    stsA(0);
    ldgA(1);
    for (int s = 0; s < NST; s++) {
        asm volatile("cp.async.wait_group 0;" ::: "memory");
        __syncthreads();     // B(s) visible; A(s) STS visible; compute(s-1) done
        if (s + 1 < NST) {
            cpaB(s + 1);                 // buf[(s+1)&1]: compute(s-1) done with it
            stsA(s + 1);
            if (s + 2 < NST) ldgA(s + 2);
        }
        compute(s);
    }
    __syncthreads();   // tiles dead; reuse smem for scores overlay

    // ---- epilogue: combine acc (unscale lo), +bias, sigmoid, overlay ----
    float* sc = (float*)(smem + OFF_PK);
    #pragma unroll
    for (int mi = 0; mi < 2; mi++) {
        int tr = wm * 32 + mi * 16 + (lane >> 2);
        #pragma unroll
        for (int ni = 0; ni < 8; ni++) {
            int e = wn * 64 + ni * 8 + (lane & 3) * 2;
            float s0 = fmaf(accL[mi][ni][0], ILSC, accH[mi][ni][0]) + bs[e];
            float s1 = fmaf(accL[mi][ni][1], ILSC, accH[mi][ni][1]) + bs[e + 1];
            float s2 = fmaf(accL[mi][ni][2], ILSC, accH[mi][ni][2]) + bs[e];
            float s3 = fmaf(accL[mi][ni][3], ILSC, accH[mi][ni][3]) + bs[e + 1];
            float2 v0, v1;
            v0.x = 1.0f / (1.0f + expf(-s0));
            v0.y = 1.0f / (1.0f + expf(-s1));
            v1.x = 1.0f / (1.0f + expf(-s2));
            v1.y = 1.0f / (1.0f + expf(-s3));
            *(float2*)&sc[tr * SC_STRIDE + e]       = v0;
            *(float2*)&sc[(tr + 8) * SC_STRIDE + e] = v1;
        }
    }
    __syncthreads();

    // ---- routing: warp per token, 8 tokens per warp ----
    for (int it = 0; it < 8; it++) {
        const int t = wid * 8 + it;
        const float* row = sc + t * SC_STRIDE;

        float orig[NGRP], rsc[NGRP];
        #pragma unroll
        for (int s = 0; s < NGRP; s++) {
            float sg = row[s * 32 + lane];
            orig[s] = sg;
            rsc[s] = sg + bs[s * 32 + lane];
        }

        // group score = top-2 sum (ties -> lower expert index)
        float gs[NGRP];
        #pragma unroll
        for (int g = 0; g < NGRP; g++) {
            float m1 = rsc[g];
            int l1 = lane;
            #pragma unroll
            for (int off = 16; off >= 1; off >>= 1) {
                float ov = __shfl_xor_sync(0xffffffffu, m1, off);
                int ol = __shfl_xor_sync(0xffffffffu, l1, off);
                if (ov > m1 || (ov == m1 && ol < l1)) { m1 = ov; l1 = ol; }
            }
            float v2 = (lane == l1) ? -INFINITY : rsc[g];
            #pragma unroll
            for (int off = 16; off >= 1; off >>= 1)
                v2 = fmaxf(v2, __shfl_xor_sync(0xffffffffu, v2, off));
            gs[g] = m1 + v2;
        }

        // keep top-4 groups (ties -> lower group index)
        float mv[NGRP];
        #pragma unroll
        for (int g = 0; g < NGRP; g++) {
            int cnt = 0;
            #pragma unroll
            for (int h = 0; h < NGRP; h++)
                cnt += (gs[h] > gs[g]) || (gs[h] == gs[g] && h < g);
            mv[g] = (cnt < TOPG) ? rsc[g] : -INFINITY;
        }

        // iterative top-8 (ties -> lower expert index)
        float wsel[TOPK];
        int esel[TOPK];
        #pragma unroll
        for (int k = 0; k < TOPK; k++) {
            float bv2 = -INFINITY; int be = NEXP; float bo = 0.0f;
            #pragma unroll
            for (int s = 0; s < NGRP; s++)
                if (mv[s] > bv2) { bv2 = mv[s]; be = s * 32 + lane; bo = orig[s]; }
            #pragma unroll
            for (int off = 16; off >= 1; off >>= 1) {
                float ov = __shfl_xor_sync(0xffffffffu, bv2, off);
                int oe = __shfl_xor_sync(0xffffffffu, be, off);
                float oo = __shfl_xor_sync(0xffffffffu, bo, off);
                if (ov > bv2 || (ov == bv2 && oe < be)) { bv2 = ov; be = oe; bo = oo; }
            }
            wsel[k] = bo;
            esel[k] = be;
            if ((be & 31) == lane) {
                int bslot = be >> 5;
                #pragma unroll
                for (int s = 0; s < NGRP; s++)
                    if (s == bslot) mv[s] = -INFINITY;
            }
        }

        float tot = 0.0f;
        #pragma unroll
        for (int k = 0; k < TOPK; k++) tot += wsel[k];
        float inv = RSCALE / tot;

        const int gt = m0 + t;
        #pragma unroll
        for (int k = 0; k < TOPK; k++) {
            if (lane == k) {
                out[(size_t)gt * TOPK + k] = wsel[k] * inv;
                if (with_idx)
                    out[(size_t)N * TOPK + (size_t)gt * TOPK + k] = (float)esel[k];
            }
        }
    }
}

// ---------------------------------------------------------------------------
extern "C" void kernel_launch(void* const* d_in, const int* in_sizes, int n_in,
                              void* d_out, int out_size)
{
    const float* x    = (const float*)d_in[0];
    const float* w    = (const float*)d_in[1];
    const float* bias = (const float*)d_in[2];
    float* out = (float*)d_out;

    int N = in_sizes[0] / HID;
    int with_idx = (out_size >= 2 * N * TOPK) ? 1 : 0;

    uint2* wpk = nullptr;
    cudaGetSymbolAddress((void**)&wpk, g_wpk);

    split_w_kernel<<<NEXP * HID / 4 / 512, 512>>>(w, wpk);

    cudaFuncSetAttribute(gate_fused_kernel,
                         cudaFuncAttributeMaxDynamicSharedMemorySize, SMEM_TOTAL);
    gate_fused_kernel<<<N / MT, 256, SMEM_TOTAL>>>(x, wpk, bias, out, N, with_idx);
}